// round 11
// baseline (speedup 1.0000x reference)
#include <cuda_runtime.h>

#define N_NODES 50000
#define N_EDGES 800000
#define E_TOT   850000
#define F_IN    128
#define H1      4
#define HC1     256
#define C2      64
#define NGRAPH  500
#define NCLS    10
#define NEG     0.2f

// ---------------- scratch (device globals; no allocation allowed) ----------------
__device__ __align__(16) float g_h1[N_NODES * HC1];
__device__ __align__(16) float g_out1[N_NODES * HC1];
__device__ __align__(16) float g_als1[N_NODES * H1];
__device__ __align__(16) float g_ald1[N_NODES * H1];

__device__ __align__(16) float g_h2[N_NODES * C2];
__device__ __align__(16) float g_out2[N_NODES * C2];
__device__ __align__(16) float g_als2[N_NODES];
__device__ __align__(16) float g_ald2[N_NODES];

__device__ __align__(16) float g_pool[NGRAPH * C2];

// CSR by destination
__device__ int g_deg[N_NODES];
__device__ int g_ptr[N_NODES + 1];
__device__ int g_fill[N_NODES];
__device__ int g_csr[E_TOT];          // src node per incoming edge

__device__ __forceinline__ void red_add_v4(float* addr, float4 v) {
    asm volatile("red.global.add.v4.f32 [%0], {%1,%2,%3,%4};"
                 :: "l"(addr), "f"(v.x), "f"(v.y), "f"(v.z), "f"(v.w) : "memory");
}
__device__ __forceinline__ float lrelu(float e) { return e > 0.f ? e : NEG * e; }

// online softmax update: m running max, s running sum of exp(e-m)
__device__ __forceinline__ void onl(float& m, float& s, float e) {
    float mn = fmaxf(m, e);
    s = s * __expf(m - mn) + __expf(e - mn);
    m = mn;
}
// combine two (m,s) states
__device__ __forceinline__ void comb(float& m, float& s, float mo, float so) {
    float mn = fmaxf(m, mo);
    s = s * __expf(m - mn) + so * __expf(mo - mn);
    m = mn;
}

// ---------------- init: zero degree + pool ----------------
__global__ void k_init() {
    int idx = blockIdx.x * blockDim.x + threadIdx.x;
    if (idx < N_NODES) g_deg[idx] = 0;
    if (idx < NGRAPH * C2) g_pool[idx] = 0.f;
}

// ---------------- CSR build ----------------
__global__ void k_deg(const int* __restrict__ ei) {
    int idx = blockIdx.x * blockDim.x + threadIdx.x;
    if (idx >= E_TOT) return;
    int d = (idx < N_EDGES) ? ei[N_EDGES + idx] : (idx - N_EDGES);
    atomicAdd(&g_deg[d], 1);
}

#define SCAN_B 1024
__global__ void k_scan() {
    __shared__ int sm[SCAN_B];
    __shared__ int carry;
    int t = threadIdx.x;
    if (t == 0) carry = 0;
    __syncthreads();
    for (int base = 0; base < N_NODES; base += SCAN_B) {
        int i = base + t;
        int v = (i < N_NODES) ? g_deg[i] : 0;
        sm[t] = v;
        __syncthreads();
#pragma unroll
        for (int off = 1; off < SCAN_B; off <<= 1) {
            int u = (t >= off) ? sm[t - off] : 0;
            __syncthreads();
            sm[t] += u;
            __syncthreads();
        }
        int excl = carry + sm[t] - v;
        if (i < N_NODES) { g_ptr[i] = excl; g_fill[i] = excl; }
        __syncthreads();
        if (t == SCAN_B - 1) carry += sm[t];
        __syncthreads();
    }
    if (t == 0) g_ptr[N_NODES] = carry;
}

__global__ void k_fill(const int* __restrict__ ei) {
    int idx = blockIdx.x * blockDim.x + threadIdx.x;
    if (idx >= E_TOT) return;
    int s, d;
    if (idx < N_EDGES) { s = ei[idx]; d = ei[N_EDGES + idx]; }
    else               { s = idx - N_EDGES; d = s; }
    int pos = atomicAdd(&g_fill[d], 1);
    g_csr[pos] = s;
}

// ---------------- GEMM1: h1 = x @ W1, fused a_src/a_dst projections ----------------
__global__ void k_gemm1(const float* __restrict__ x, const float* __restrict__ W1,
                        const float* __restrict__ as1, const float* __restrict__ ad1) {
    __shared__ float xs[4][F_IN];
    int t = threadIdx.x, y = threadIdx.y;
    int node = blockIdx.x * 4 + y;
    xs[y][t]      = x[node * F_IN + t];
    xs[y][t + 64] = x[node * F_IN + t + 64];
    __syncthreads();
    const float4* W1v = (const float4*)W1;
    float4 acc = make_float4(0.f, 0.f, 0.f, 0.f);
#pragma unroll 8
    for (int k = 0; k < F_IN; k++) {
        float xv = xs[y][k];
        float4 w = W1v[k * 64 + t];
        acc.x += xv * w.x; acc.y += xv * w.y; acc.z += xv * w.z; acc.w += xv * w.w;
    }
    ((float4*)g_h1)[node * 64 + t] = acc;
    int c0 = 4 * t;
    float ps = acc.x * as1[c0] + acc.y * as1[c0 + 1] + acc.z * as1[c0 + 2] + acc.w * as1[c0 + 3];
    float pd = acc.x * ad1[c0] + acc.y * ad1[c0 + 1] + acc.z * ad1[c0 + 2] + acc.w * ad1[c0 + 3];
#pragma unroll
    for (int off = 8; off; off >>= 1) {
        ps += __shfl_xor_sync(0xffffffffu, ps, off, 16);
        pd += __shfl_xor_sync(0xffffffffu, pd, off, 16);
    }
    if ((t & 15) == 0) {
        int h = t >> 4;
        g_als1[node * H1 + h] = ps;
        g_ald1[node * H1 + h] = pd;
    }
}

// ---------------- fused GAT layer 1: warp per dst node ----------------
__global__ void k_gat1() {
    int warp = (blockIdx.x * blockDim.x + threadIdx.x) >> 5;
    int lane = threadIdx.x & 31;
    if (warp >= N_NODES) return;
    int d = warp;
    int beg = g_ptr[d], end = g_ptr[d + 1];
    float4 ald = ((const float4*)g_ald1)[d];

    // online softmax stats per lane (4 heads)
    float4 m = make_float4(-1e30f, -1e30f, -1e30f, -1e30f);
    float4 ss = make_float4(0.f, 0.f, 0.f, 0.f);
    for (int i = beg + lane; i < end; i += 32) {
        int s = __ldg(&g_csr[i]);
        float4 a = ((const float4*)g_als1)[s];
        onl(m.x, ss.x, lrelu(a.x + ald.x));
        onl(m.y, ss.y, lrelu(a.y + ald.y));
        onl(m.z, ss.z, lrelu(a.z + ald.z));
        onl(m.w, ss.w, lrelu(a.w + ald.w));
    }
#pragma unroll
    for (int off = 16; off; off >>= 1) {
        float mx = __shfl_xor_sync(0xffffffffu, m.x, off);
        float sx = __shfl_xor_sync(0xffffffffu, ss.x, off);
        float my = __shfl_xor_sync(0xffffffffu, m.y, off);
        float sy = __shfl_xor_sync(0xffffffffu, ss.y, off);
        float mz = __shfl_xor_sync(0xffffffffu, m.z, off);
        float sz = __shfl_xor_sync(0xffffffffu, ss.z, off);
        float mw = __shfl_xor_sync(0xffffffffu, m.w, off);
        float sw = __shfl_xor_sync(0xffffffffu, ss.w, off);
        comb(m.x, ss.x, mx, sx);
        comb(m.y, ss.y, my, sy);
        comb(m.z, ss.z, mz, sz);
        comb(m.w, ss.w, mw, sw);
    }
    float4 inv;
    inv.x = 1.f / (ss.x + 1e-16f);
    inv.y = 1.f / (ss.y + 1e-16f);
    inv.z = 1.f / (ss.z + 1e-16f);
    inv.w = 1.f / (ss.w + 1e-16f);

    // aggregation: lane owns channels [4*lane,4*lane+3] and [4*(lane+32)..]
    float4 acc0 = make_float4(0.f, 0.f, 0.f, 0.f);
    float4 acc1 = make_float4(0.f, 0.f, 0.f, 0.f);
    for (int i = beg; i < end; i++) {
        int s = __ldg(&g_csr[i]);        // warp-uniform broadcast
        float4 a = ((const float4*)g_als1)[s];
        float4 al;
        al.x = __expf(lrelu(a.x + ald.x) - m.x) * inv.x;
        al.y = __expf(lrelu(a.y + ald.y) - m.y) * inv.y;
        al.z = __expf(lrelu(a.z + ald.z) - m.z) * inv.z;
        al.w = __expf(lrelu(a.w + ald.w) - m.w) * inv.w;
        const float4* hs = (const float4*)(g_h1 + (size_t)s * HC1);
        float4 h0 = hs[lane];
        float4 h1v = hs[lane + 32];
        float a0 = (lane < 16) ? al.x : al.y;   // head of channels 4*lane
        float a1 = (lane < 16) ? al.z : al.w;   // head of channels 4*(lane+32)
        acc0.x += a0 * h0.x;  acc0.y += a0 * h0.y;  acc0.z += a0 * h0.z;  acc0.w += a0 * h0.w;
        acc1.x += a1 * h1v.x; acc1.y += a1 * h1v.y; acc1.z += a1 * h1v.z; acc1.w += a1 * h1v.w;
    }
    float4* od = (float4*)(g_out1 + (size_t)d * HC1);
    od[lane]      = acc0;
    od[lane + 32] = acc1;
}

// ---------------- GEMM2: h2 = relu(out1 + b1) @ W2, fused projections ----------------
__global__ void k_gemm2(const float* __restrict__ W2, const float* __restrict__ b1,
                        const float* __restrict__ as2, const float* __restrict__ ad2) {
    __shared__ float rs[8][HC1];
    int t = threadIdx.x, y = threadIdx.y;
    int tid = t + 16 * y;
    int nodeBase = blockIdx.x * 8;
    for (int idx = tid; idx < 8 * HC1; idx += 128) {
        int nl = idx >> 8, k = idx & 255;
        float v = g_out1[(size_t)(nodeBase + nl) * HC1 + k] + b1[k];
        rs[nl][k] = v > 0.f ? v : 0.f;
    }
    __syncthreads();
    int node = nodeBase + y;
    const float4* W2v = (const float4*)W2;
    float4 acc = make_float4(0.f, 0.f, 0.f, 0.f);
#pragma unroll 8
    for (int k = 0; k < HC1; k++) {
        float rv = rs[y][k];
        float4 w = W2v[k * 16 + t];
        acc.x += rv * w.x; acc.y += rv * w.y; acc.z += rv * w.z; acc.w += rv * w.w;
    }
    ((float4*)g_h2)[node * 16 + t] = acc;
    int c0 = 4 * t;
    float ps = acc.x * as2[c0] + acc.y * as2[c0 + 1] + acc.z * as2[c0 + 2] + acc.w * as2[c0 + 3];
    float pd = acc.x * ad2[c0] + acc.y * ad2[c0 + 1] + acc.z * ad2[c0 + 2] + acc.w * ad2[c0 + 3];
#pragma unroll
    for (int off = 8; off; off >>= 1) {
        ps += __shfl_xor_sync(0xffffffffu, ps, off, 16);
        pd += __shfl_xor_sync(0xffffffffu, pd, off, 16);
    }
    if (t == 0) { g_als2[node] = ps; g_ald2[node] = pd; }
}

// ---------------- fused GAT layer 2: warp per dst node (1 head) ----------------
__global__ void k_gat2() {
    int warp = (blockIdx.x * blockDim.x + threadIdx.x) >> 5;
    int lane = threadIdx.x & 31;
    if (warp >= N_NODES) return;
    int d = warp;
    int beg = g_ptr[d], end = g_ptr[d + 1];
    float ald = g_ald2[d];

    float m = -1e30f, ssum = 0.f;
    for (int i = beg + lane; i < end; i += 32) {
        int s = __ldg(&g_csr[i]);
        onl(m, ssum, lrelu(g_als2[s] + ald));
    }
#pragma unroll
    for (int off = 16; off; off >>= 1) {
        float mo = __shfl_xor_sync(0xffffffffu, m, off);
        float so = __shfl_xor_sync(0xffffffffu, ssum, off);
        comb(m, ssum, mo, so);
    }
    float inv = 1.f / (ssum + 1e-16f);

    float2 acc = make_float2(0.f, 0.f);
    for (int i = beg; i < end; i++) {
        int s = __ldg(&g_csr[i]);
        float alpha = __expf(lrelu(g_als2[s] + ald) - m) * inv;
        float2 h = ((const float2*)(g_h2 + (size_t)s * C2))[lane];
        acc.x += alpha * h.x;
        acc.y += alpha * h.y;
    }
    ((float2*)(g_out2 + (size_t)d * C2))[lane] = acc;
}

// ---------------- global add pool (v4 red) ----------------
__global__ void k_pool(const int* __restrict__ batch, const float* __restrict__ b2) {
    int idx = blockIdx.x * blockDim.x + threadIdx.x;  // over N_NODES*16 float4s
    if (idx >= N_NODES * 16) return;
    int n = idx >> 4, c4 = idx & 15;
    int g = batch[n];
    float4 v = ((const float4*)g_out2)[idx];
    float4 bb = ((const float4*)b2)[c4];
    v.x += bb.x; v.y += bb.y; v.z += bb.z; v.w += bb.w;
    red_add_v4(g_pool + g * C2 + 4 * c4, v);
}

// ---------------- classifier + log_softmax ----------------
__global__ void k_cls(const float* __restrict__ fcw, const float* __restrict__ fcb,
                      float* __restrict__ out) {
    int g = blockIdx.x;
    int t = threadIdx.x;
    __shared__ float lg[NCLS];
    __shared__ float s_m, s_lse;
    if (t < NCLS) {
        float acc = fcb[t];
#pragma unroll
        for (int k = 0; k < C2; k++) acc += g_pool[g * C2 + k] * fcw[k * NCLS + t];
        lg[t] = acc;
    }
    __syncthreads();
    if (t == 0) {
        float m = lg[0];
        for (int i = 1; i < NCLS; i++) m = fmaxf(m, lg[i]);
        float s = 0.f;
        for (int i = 0; i < NCLS; i++) s += expf(lg[i] - m);
        s_m = m; s_lse = logf(s);
    }
    __syncthreads();
    if (t < NCLS) out[g * NCLS + t] = lg[t] - s_m - s_lse;
}

// ---------------- launch ----------------
extern "C" void kernel_launch(void* const* d_in, const int* in_sizes, int n_in,
                              void* d_out, int out_size) {
    const float* x    = (const float*)d_in[0];
    const int*   ei   = (const int*)d_in[1];
    const int*   bat  = (const int*)d_in[2];
    const float* W1   = (const float*)d_in[3];
    const float* as1  = (const float*)d_in[4];
    const float* ad1  = (const float*)d_in[5];
    const float* b1   = (const float*)d_in[6];
    const float* W2   = (const float*)d_in[7];
    const float* as2  = (const float*)d_in[8];
    const float* ad2  = (const float*)d_in[9];
    const float* b2   = (const float*)d_in[10];
    const float* fcw  = (const float*)d_in[11];
    const float* fcb  = (const float*)d_in[12];
    float* out = (float*)d_out;

    int eb = (E_TOT + 255) / 256;
    k_init<<<(NGRAPH * C2 + 255) / 256 > (N_NODES + 255) / 256 ?
             (NGRAPH * C2 + 255) / 256 : (N_NODES + 255) / 256, 256>>>();
    k_deg<<<eb, 256>>>(ei);
    k_scan<<<1, SCAN_B>>>();
    k_fill<<<eb, 256>>>(ei);
    k_gemm1<<<N_NODES / 4, dim3(64, 4)>>>(x, W1, as1, ad1);
    k_gat1<<<(N_NODES * 32 + 255) / 256, 256>>>();
    k_gemm2<<<N_NODES / 8, dim3(16, 8)>>>(W2, b1, as2, ad2);
    k_gat2<<<(N_NODES * 32 + 255) / 256, 256>>>();
    k_pool<<<(N_NODES * 16 + 255) / 256, 256>>>(bat, b2);
    k_cls<<<NGRAPH, 32>>>(fcw, fcb, out);
}

// round 12
// speedup vs baseline: 1.6562x; 1.6562x over previous
#include <cuda_runtime.h>

#define N_NODES 50000
#define N_EDGES 800000
#define E_TOT   850000
#define F_IN    128
#define H1      4
#define HC1     256
#define C2      64
#define NGRAPH  500
#define NCLS    10
#define NEG     0.2f

// ---------------- scratch (device globals; no allocation allowed) ----------------
__device__ __align__(16) float g_h1[N_NODES * HC1];
__device__ __align__(16) float g_out1[N_NODES * HC1];
__device__ __align__(16) float g_als1[N_NODES * H1];
__device__ __align__(16) float g_ald1[N_NODES * H1];

__device__ __align__(16) float g_h2[N_NODES * C2];
__device__ __align__(16) float g_als2[N_NODES];
__device__ __align__(16) float g_ald2[N_NODES];

__device__ __align__(16) float g_pool[NGRAPH * C2];
__device__ int g_cnt[NGRAPH];

// CSR by destination
__device__ int g_deg[N_NODES];
__device__ int g_ptr[N_NODES + 1];
__device__ int g_fill[N_NODES];
__device__ int g_csr[E_TOT];

__device__ __forceinline__ void red_add_v2(float* addr, float a, float b) {
    asm volatile("red.global.add.v2.f32 [%0], {%1,%2};"
                 :: "l"(addr), "f"(a), "f"(b) : "memory");
}
__device__ __forceinline__ float lrelu(float e) { return e > 0.f ? e : NEG * e; }

// ---- packed f32x2 helpers (sm_100+) ----
__device__ __forceinline__ unsigned long long pk2(float lo, float hi) {
    unsigned long long r;
    asm("mov.b64 %0, {%1,%2};" : "=l"(r) : "f"(lo), "f"(hi));
    return r;
}
__device__ __forceinline__ float2 upk2(unsigned long long v) {
    float2 r;
    asm("mov.b64 {%0,%1}, %2;" : "=f"(r.x), "=f"(r.y) : "l"(v));
    return r;
}
__device__ __forceinline__ void ffma2(unsigned long long& acc, unsigned long long a,
                                      unsigned long long b) {
    asm("fma.rn.f32x2 %0, %1, %2, %0;" : "+l"(acc) : "l"(a), "l"(b));
}

// ---------------- init: zero degree + pool + cnt ----------------
__global__ void k_init() {
    int idx = blockIdx.x * blockDim.x + threadIdx.x;
    if (idx < N_NODES) g_deg[idx] = 0;
    if (idx < NGRAPH * C2) g_pool[idx] = 0.f;
    if (idx < NGRAPH) g_cnt[idx] = 0;
}

// ---------------- CSR build + per-graph node counts ----------------
__global__ void k_deg(const int* __restrict__ ei, const int* __restrict__ bat) {
    int idx = blockIdx.x * blockDim.x + threadIdx.x;
    if (idx < N_NODES) atomicAdd(&g_cnt[bat[idx]], 1);
    if (idx >= E_TOT) return;
    int d = (idx < N_EDGES) ? ei[N_EDGES + idx] : (idx - N_EDGES);
    atomicAdd(&g_deg[d], 1);
}

#define SCAN_B 1024
__global__ void k_scan() {
    __shared__ int sm[SCAN_B];
    __shared__ int carry;
    int t = threadIdx.x;
    if (t == 0) carry = 0;
    __syncthreads();
    for (int base = 0; base < N_NODES; base += SCAN_B) {
        int i = base + t;
        int v = (i < N_NODES) ? g_deg[i] : 0;
        sm[t] = v;
        __syncthreads();
#pragma unroll
        for (int off = 1; off < SCAN_B; off <<= 1) {
            int u = (t >= off) ? sm[t - off] : 0;
            __syncthreads();
            sm[t] += u;
            __syncthreads();
        }
        int excl = carry + sm[t] - v;
        if (i < N_NODES) { g_ptr[i] = excl; g_fill[i] = excl; }
        __syncthreads();
        if (t == SCAN_B - 1) carry += sm[t];
        __syncthreads();
    }
    if (t == 0) g_ptr[N_NODES] = carry;
}

__global__ void k_fill(const int* __restrict__ ei) {
    int idx = blockIdx.x * blockDim.x + threadIdx.x;
    if (idx >= E_TOT) return;
    int s, d;
    if (idx < N_EDGES) { s = ei[idx]; d = ei[N_EDGES + idx]; }
    else               { s = idx - N_EDGES; d = s; }
    int pos = atomicAdd(&g_fill[d], 1);
    g_csr[pos] = s;
}

// ---------------- GEMM1: h1 = x @ W1 (f32x2), fused a_src/a_dst projections ----------------
__global__ void k_gemm1(const float* __restrict__ x, const float* __restrict__ W1,
                        const float* __restrict__ as1, const float* __restrict__ ad1) {
    __shared__ float xs[4][F_IN];
    int t = threadIdx.x, y = threadIdx.y;
    int node = blockIdx.x * 4 + y;
    xs[y][t]      = x[node * F_IN + t];
    xs[y][t + 64] = x[node * F_IN + t + 64];
    __syncthreads();
    const float4* W1v = (const float4*)W1;
    unsigned long long a01 = 0ull, a23 = 0ull;   // (0.f,0.f) packed
#pragma unroll 8
    for (int k = 0; k < F_IN; k++) {
        float xv = xs[y][k];
        unsigned long long xp = pk2(xv, xv);
        float4 w = W1v[k * 64 + t];
        ffma2(a01, xp, pk2(w.x, w.y));
        ffma2(a23, xp, pk2(w.z, w.w));
    }
    float2 axy = upk2(a01), azw = upk2(a23);
    float4 acc = make_float4(axy.x, axy.y, azw.x, azw.y);
    ((float4*)g_h1)[node * 64 + t] = acc;
    int c0 = 4 * t;
    float ps = acc.x * as1[c0] + acc.y * as1[c0 + 1] + acc.z * as1[c0 + 2] + acc.w * as1[c0 + 3];
    float pd = acc.x * ad1[c0] + acc.y * ad1[c0 + 1] + acc.z * ad1[c0 + 2] + acc.w * ad1[c0 + 3];
#pragma unroll
    for (int off = 8; off; off >>= 1) {
        ps += __shfl_xor_sync(0xffffffffu, ps, off, 16);
        pd += __shfl_xor_sync(0xffffffffu, pd, off, 16);
    }
    if ((t & 15) == 0) {
        int h = t >> 4;
        g_als1[node * H1 + h] = ps;
        g_ald1[node * H1 + h] = pd;
    }
}

// ---------------- fused GAT layer 1: warp per dst node, single pass, no max ----------------
__global__ void k_gat1() {
    int warp = (blockIdx.x * blockDim.x + threadIdx.x) >> 5;
    int lane = threadIdx.x & 31;
    if (warp >= N_NODES) return;
    int d = warp;
    int beg = g_ptr[d], end = g_ptr[d + 1];
    float4 ald = ((const float4*)g_ald1)[d];
    bool lo = lane < 16;
    float ad0 = lo ? ald.x : ald.y;   // head of channels [4*lane .. 4*lane+3]
    float ad1v = lo ? ald.z : ald.w;  // head of channels [4*(lane+32) ..]

    float4 acc0 = make_float4(0.f, 0.f, 0.f, 0.f);
    float4 acc1 = make_float4(0.f, 0.f, 0.f, 0.f);
    float s0 = 0.f, s1 = 0.f;

    int i = beg;
    for (; i + 2 <= end; i += 2) {
        int sA = __ldg(&g_csr[i]);
        int sB = __ldg(&g_csr[i + 1]);
        float4 aA = ((const float4*)g_als1)[sA];
        float4 aB = ((const float4*)g_als1)[sB];
        const float4* hA = (const float4*)(g_h1 + (size_t)sA * HC1);
        const float4* hB = (const float4*)(g_h1 + (size_t)sB * HC1);
        float4 hA0 = hA[lane], hA1 = hA[lane + 32];
        float4 hB0 = hB[lane], hB1 = hB[lane + 32];
        float wA0 = __expf(lrelu((lo ? aA.x : aA.y) + ad0));
        float wA1 = __expf(lrelu((lo ? aA.z : aA.w) + ad1v));
        float wB0 = __expf(lrelu((lo ? aB.x : aB.y) + ad0));
        float wB1 = __expf(lrelu((lo ? aB.z : aB.w) + ad1v));
        s0 += wA0 + wB0; s1 += wA1 + wB1;
        acc0.x += wA0 * hA0.x; acc0.y += wA0 * hA0.y; acc0.z += wA0 * hA0.z; acc0.w += wA0 * hA0.w;
        acc0.x += wB0 * hB0.x; acc0.y += wB0 * hB0.y; acc0.z += wB0 * hB0.z; acc0.w += wB0 * hB0.w;
        acc1.x += wA1 * hA1.x; acc1.y += wA1 * hA1.y; acc1.z += wA1 * hA1.z; acc1.w += wA1 * hA1.w;
        acc1.x += wB1 * hB1.x; acc1.y += wB1 * hB1.y; acc1.z += wB1 * hB1.z; acc1.w += wB1 * hB1.w;
    }
    if (i < end) {
        int s = __ldg(&g_csr[i]);
        float4 a = ((const float4*)g_als1)[s];
        const float4* hs = (const float4*)(g_h1 + (size_t)s * HC1);
        float4 h0 = hs[lane], h1v = hs[lane + 32];
        float w0 = __expf(lrelu((lo ? a.x : a.y) + ad0));
        float w1 = __expf(lrelu((lo ? a.z : a.w) + ad1v));
        s0 += w0; s1 += w1;
        acc0.x += w0 * h0.x; acc0.y += w0 * h0.y; acc0.z += w0 * h0.z; acc0.w += w0 * h0.w;
        acc1.x += w1 * h1v.x; acc1.y += w1 * h1v.y; acc1.z += w1 * h1v.z; acc1.w += w1 * h1v.w;
    }
    float i0 = 1.f / (s0 + 1e-16f);
    float i1 = 1.f / (s1 + 1e-16f);
    acc0.x *= i0; acc0.y *= i0; acc0.z *= i0; acc0.w *= i0;
    acc1.x *= i1; acc1.y *= i1; acc1.z *= i1; acc1.w *= i1;
    float4* od = (float4*)(g_out1 + (size_t)d * HC1);
    od[lane]      = acc0;
    od[lane + 32] = acc1;
}

// ---------------- GEMM2: h2 = relu(out1 + b1) @ W2 (f32x2), fused projections ----------------
__global__ void k_gemm2(const float* __restrict__ W2, const float* __restrict__ b1,
                        const float* __restrict__ as2, const float* __restrict__ ad2) {
    __shared__ float rs[8][HC1];
    int t = threadIdx.x, y = threadIdx.y;
    int tid = t + 16 * y;
    int nodeBase = blockIdx.x * 8;
    for (int idx = tid; idx < 8 * HC1; idx += 128) {
        int nl = idx >> 8, k = idx & 255;
        float v = g_out1[(size_t)(nodeBase + nl) * HC1 + k] + b1[k];
        rs[nl][k] = v > 0.f ? v : 0.f;
    }
    __syncthreads();
    int node = nodeBase + y;
    const float4* W2v = (const float4*)W2;
    unsigned long long a01 = 0ull, a23 = 0ull;
#pragma unroll 8
    for (int k = 0; k < HC1; k++) {
        float rv = rs[y][k];
        unsigned long long xp = pk2(rv, rv);
        float4 w = W2v[k * 16 + t];
        ffma2(a01, xp, pk2(w.x, w.y));
        ffma2(a23, xp, pk2(w.z, w.w));
    }
    float2 axy = upk2(a01), azw = upk2(a23);
    float4 acc = make_float4(axy.x, axy.y, azw.x, azw.y);
    ((float4*)g_h2)[node * 16 + t] = acc;
    int c0 = 4 * t;
    float ps = acc.x * as2[c0] + acc.y * as2[c0 + 1] + acc.z * as2[c0 + 2] + acc.w * as2[c0 + 3];
    float pd = acc.x * ad2[c0] + acc.y * ad2[c0 + 1] + acc.z * ad2[c0 + 2] + acc.w * ad2[c0 + 3];
#pragma unroll
    for (int off = 8; off; off >>= 1) {
        ps += __shfl_xor_sync(0xffffffffu, ps, off, 16);
        pd += __shfl_xor_sync(0xffffffffu, pd, off, 16);
    }
    if (t == 0) { g_als2[node] = ps; g_ald2[node] = pd; }
}

// ---------------- fused GAT layer 2 + pool scatter: warp per dst node ----------------
__global__ void k_gat2(const int* __restrict__ bat) {
    int warp = (blockIdx.x * blockDim.x + threadIdx.x) >> 5;
    int lane = threadIdx.x & 31;
    if (warp >= N_NODES) return;
    int d = warp;
    int beg = g_ptr[d], end = g_ptr[d + 1];
    float ald = g_ald2[d];

    float2 acc = make_float2(0.f, 0.f);
    float ssum = 0.f;
    int i = beg;
    for (; i + 2 <= end; i += 2) {
        int sA = __ldg(&g_csr[i]);
        int sB = __ldg(&g_csr[i + 1]);
        float aA = g_als2[sA];
        float aB = g_als2[sB];
        float2 hA = ((const float2*)(g_h2 + (size_t)sA * C2))[lane];
        float2 hB = ((const float2*)(g_h2 + (size_t)sB * C2))[lane];
        float wA = __expf(lrelu(aA + ald));
        float wB = __expf(lrelu(aB + ald));
        ssum += wA + wB;
        acc.x += wA * hA.x + wB * hB.x;
        acc.y += wA * hA.y + wB * hB.y;
    }
    if (i < end) {
        int s = __ldg(&g_csr[i]);
        float w = __expf(lrelu(g_als2[s] + ald));
        float2 h = ((const float2*)(g_h2 + (size_t)s * C2))[lane];
        ssum += w;
        acc.x += w * h.x;
        acc.y += w * h.y;
    }
    float inv = 1.f / (ssum + 1e-16f);
    int g = bat[d];
    red_add_v2(g_pool + g * C2 + 2 * lane, acc.x * inv, acc.y * inv);
}

// ---------------- classifier + log_softmax (b2 folded via node counts) ----------------
__global__ void k_cls(const float* __restrict__ fcw, const float* __restrict__ fcb,
                      const float* __restrict__ b2, float* __restrict__ out) {
    int g = blockIdx.x;
    int t = threadIdx.x;
    __shared__ float lg[NCLS];
    __shared__ float s_m, s_lse;
    if (t < NCLS) {
        float cnt = (float)g_cnt[g];
        float acc = fcb[t];
#pragma unroll
        for (int k = 0; k < C2; k++)
            acc += (g_pool[g * C2 + k] + cnt * b2[k]) * fcw[k * NCLS + t];
        lg[t] = acc;
    }
    __syncthreads();
    if (t == 0) {
        float m = lg[0];
        for (int i = 1; i < NCLS; i++) m = fmaxf(m, lg[i]);
        float s = 0.f;
        for (int i = 0; i < NCLS; i++) s += expf(lg[i] - m);
        s_m = m; s_lse = logf(s);
    }
    __syncthreads();
    if (t < NCLS) out[g * NCLS + t] = lg[t] - s_m - s_lse;
}

// ---------------- launch ----------------
extern "C" void kernel_launch(void* const* d_in, const int* in_sizes, int n_in,
                              void* d_out, int out_size) {
    const float* x    = (const float*)d_in[0];
    const int*   ei   = (const int*)d_in[1];
    const int*   bat  = (const int*)d_in[2];
    const float* W1   = (const float*)d_in[3];
    const float* as1  = (const float*)d_in[4];
    const float* ad1  = (const float*)d_in[5];
    const float* b1   = (const float*)d_in[6];
    const float* W2   = (const float*)d_in[7];
    const float* as2  = (const float*)d_in[8];
    const float* ad2  = (const float*)d_in[9];
    const float* b2   = (const float*)d_in[10];
    const float* fcw  = (const float*)d_in[11];
    const float* fcb  = (const float*)d_in[12];
    float* out = (float*)d_out;

    int eb = (E_TOT + 255) / 256;
    k_init<<<(N_NODES + 255) / 256, 256>>>();
    k_deg<<<eb, 256>>>(ei, bat);
    k_scan<<<1, SCAN_B>>>();
    k_fill<<<eb, 256>>>(ei);
    k_gemm1<<<N_NODES / 4, dim3(64, 4)>>>(x, W1, as1, ad1);
    k_gat1<<<(N_NODES * 32 + 255) / 256, 256>>>();
    k_gemm2<<<N_NODES / 8, dim3(16, 8)>>>(W2, b1, as2, ad2);
    k_gat2<<<(N_NODES * 32 + 255) / 256, 256>>>(bat);
    k_cls<<<NGRAPH, 32>>>(fcw, fcb, b2, out);
}